// round 16
// baseline (speedup 1.0000x reference)
#include <cuda_runtime.h>
#include <cuda_fp16.h>
#include <math.h>
#include <stdint.h>

#define NTOK 4096
#define HID  1024
#define FFN  2816
#define NEXP 8
#define NSLOT (NTOK * 2)

// ================= helpers =================
__device__ __forceinline__ uint32_t smem_u32(const void* p) {
    uint32_t a;
    asm("{ .reg .u64 t; cvta.to.shared.u64 t, %1; cvt.u32.u64 %0, t; }" : "=r"(a) : "l"(p));
    return a;
}

#define CP_ASYNC16(dst_u32, src_ptr) \
    asm volatile("cp.async.cg.shared.global [%0], [%1], 16;" :: "r"(dst_u32), "l"(src_ptr))

#define LDSM4(r, addr) \
    asm volatile("ldmatrix.sync.aligned.m8n8.x4.shared.b16 {%0,%1,%2,%3}, [%4];" \
        : "=r"((r)[0]), "=r"((r)[1]), "=r"((r)[2]), "=r"((r)[3]) : "r"(addr))

__device__ __forceinline__ void mma_f16(float c[4],
                                        uint32_t a0, uint32_t a1, uint32_t a2, uint32_t a3,
                                        uint32_t b0, uint32_t b1) {
    asm volatile("mma.sync.aligned.m16n8k16.row.col.f32.f16.f16.f32 "
        "{%0,%1,%2,%3}, {%4,%5,%6,%7}, {%8,%9}, {%0,%1,%2,%3};"
        : "+f"(c[0]), "+f"(c[1]), "+f"(c[2]), "+f"(c[3])
        : "r"(a0), "r"(a1), "r"(a2), "r"(a3), "r"(b0), "r"(b1));
}

__device__ __forceinline__ uint32_t h2_as_u32(__half2 h) {
    uint32_t u; asm("mov.b32 %0, %1;" : "=r"(u) : "r"(*(uint32_t*)&h)); return u;
}

// ---- mbarrier ops ----
#define MBAR_INIT(addr, cnt) \
    asm volatile("mbarrier.init.shared.b64 [%0], %1;" :: "r"(addr), "r"((uint32_t)(cnt)) : "memory")
#define MBAR_ARRIVE(addr) \
    asm volatile("mbarrier.arrive.shared.b64 _, [%0];" :: "r"(addr) : "memory")
#define CPA_ARRIVE(addr) \
    asm volatile("cp.async.mbarrier.arrive.noinc.shared.b64 [%0];" :: "r"(addr) : "memory")

#define MBAR_WAIT(mbar_addr, parity) do { \
    uint32_t _m = (uint32_t)(mbar_addr); uint32_t _p = (uint32_t)(parity); uint32_t _d; \
    asm volatile("{\n\t.reg .pred p;\n\t" \
        "mbarrier.try_wait.parity.acquire.cta.shared::cta.b64 p, [%1], %2;\n\t" \
        "selp.b32 %0, 1, 0, p;\n\t}" : "=r"(_d) : "r"(_m), "r"(_p) : "memory"); \
    if (!_d) { \
        asm volatile("{\n\t.reg .pred P1;\n\t" \
            "WL_%=:\n\t" \
            "mbarrier.try_wait.parity.acquire.cta.shared::cta.b64 P1, [%0], %1, 0x989680;\n\t" \
            "@P1 bra.uni WD_%=;\n\t" \
            "bra.uni WL_%=;\n\t" \
            "WD_%=:\n\t}" :: "r"(_m), "r"(_p) : "memory"); \
    } \
} while (0)

// ================= scratch =================
__device__ int    d_cnt[NEXP];
__device__ int    d_cntf[NEXP];
__device__ int    d_off[NEXP];
__device__ int    d_tok_expert[NSLOT];
__device__ float  d_tok_w[NSLOT];
__device__ int    d_tok_pos[NSLOT];
__device__ int    d_slot_token[NSLOT];
__device__ float  d_slot_w[NSLOT];

__device__ __half d_x16[(size_t)NTOK * HID];
__device__ __half d_w1h[(size_t)NEXP * FFN * HID];
__device__ __half d_w3h[(size_t)NEXP * FFN * HID];
__device__ __half d_w2h[(size_t)NEXP * HID * FFN];
__device__ __half d_H16[(size_t)NSLOT * FFN];

// ================= fp32 -> fp16 =================
__device__ __forceinline__ void cvt8_body(const float* __restrict__ src,
                                          __half* __restrict__ dst, int i) {
    const float4* s4 = (const float4*)src + (size_t)i * 2;
    float4 a = s4[0], b = s4[1];
    uint4 o;
    o.x = h2_as_u32(__floats2half2_rn(a.x, a.y));
    o.y = h2_as_u32(__floats2half2_rn(a.z, a.w));
    o.z = h2_as_u32(__floats2half2_rn(b.x, b.y));
    o.w = h2_as_u32(__floats2half2_rn(b.z, b.w));
    ((uint4*)dst)[i] = o;
}

// ================= fused gate + cvt(x,w1,w3) =================
#define GATE_BLKS (NTOK / 2)

__global__ void __launch_bounds__(256)
gate_cvt13_kernel(const float* __restrict__ x, const float* __restrict__ gw,
                  const float* __restrict__ w1, const float* __restrict__ w3,
                  __half* __restrict__ x16, __half* __restrict__ w1h,
                  __half* __restrict__ w3h) {
    int bx = blockIdx.x;
    int tid = threadIdx.x;
    if (bx < GATE_BLKS) {
        int half = tid >> 7;
        int htid = tid & 127;
        int t = bx * 2 + half;
        const float* xr = x + (size_t)t * HID;
        float part[NEXP];
#pragma unroll
        for (int e = 0; e < NEXP; e++) part[e] = 0.f;
#pragma unroll
        for (int i = 0; i < HID / 128; i++) {
            float xv = xr[htid + i * 128];
#pragma unroll
            for (int e = 0; e < NEXP; e++) part[e] += xv * gw[e * HID + htid + i * 128];
        }
        __shared__ float sh[8][NEXP];
        int lane = tid & 31, w = tid >> 5;
#pragma unroll
        for (int e = 0; e < NEXP; e++) {
            float v = part[e];
            for (int s = 16; s > 0; s >>= 1) v += __shfl_down_sync(0xffffffffu, v, s);
            if (lane == 0) sh[w][e] = v;
        }
        __syncthreads();
        if (htid == 0) {
            int wb = half * 4;
            float logit[NEXP];
#pragma unroll
            for (int e = 0; e < NEXP; e++)
                logit[e] = sh[wb][e] + sh[wb + 1][e] + sh[wb + 2][e] + sh[wb + 3][e];
            int i0 = 0;
            for (int e = 1; e < NEXP; e++) if (logit[e] > logit[i0]) i0 = e;
            int i1 = -1;
            for (int e = 0; e < NEXP; e++) {
                if (e == i0) continue;
                if (i1 < 0 || logit[e] > logit[i1]) i1 = e;
            }
            float p1 = expf(logit[i1] - logit[i0]);
            float inv = 1.f / (1.f + p1);
            int q0 = atomicAdd(&d_cnt[i0], 1);
            int q1 = atomicAdd(&d_cnt[i1], 1);
            d_tok_expert[t * 2 + 0] = i0;  d_tok_expert[t * 2 + 1] = i1;
            d_tok_w[t * 2 + 0] = inv;      d_tok_w[t * 2 + 1] = p1 * inv;
            d_tok_pos[t * 2 + 0] = q0;     d_tok_pos[t * 2 + 1] = q1;
        }
    } else {
        const int NW8 = NEXP * FFN * HID / 8;
        const int NX8 = NTOK * HID / 8;
        int i = (bx - GATE_BLKS) * 256 + tid;
        if (i < NW8)                 cvt8_body(w1, w1h, i);
        else if (i < 2 * NW8)        cvt8_body(w3, w3h, i - NW8);
        else if (i < 2 * NW8 + NX8)  cvt8_body(x,  x16, i - 2 * NW8);
    }
}

// ================= scan (+ snapshot & reset) =================
__global__ void scan_kernel() {
    if (threadIdx.x == 0) {
        int s = 0;
        for (int e = 0; e < NEXP; e++) {
            int c = d_cnt[e];
            d_off[e] = s;
            d_cntf[e] = c;
            s += c;
            d_cnt[e] = 0;
        }
    }
}

// ================= fused scatter + zero(out) =================
#define SCAT_BLKS (NSLOT / 256)

__global__ void __launch_bounds__(256)
scatter_zero_kernel(float* __restrict__ out) {
    int bx = blockIdx.x;
    int tid = threadIdx.x;
    if (bx < SCAT_BLKS) {
        int idx = bx * 256 + tid;
        int e = d_tok_expert[idx];
        int slot = d_off[e] + d_tok_pos[idx];
        d_slot_token[slot] = idx >> 1;
        d_slot_w[slot] = d_tok_w[idx];
    } else {
        int i = (bx - SCAT_BLKS) * 256 + tid;
        if (i < NTOK * HID / 4) ((float4*)out)[i] = make_float4(0.f, 0.f, 0.f, 0.f);
    }
}

// ================= tensor GEMMs: 512 thr/CTA, 1 CTA/SM, 4-stage mbarrier pipe =================
// gemm1: CTA 256Mx64N dual (w1+w3); 16 warps 4m x 4n; warp 64x16 dual.
// gemm2: CTA 256Mx128N; 16 warps 4m x 4n; warp 64x32.
// Stage = 256*144 (A) + 128*144 (B) = 55296 B; 4 stages = 221184 B -> 1 CTA/SM.
#define PITCH 144u
#define A_STG (256 * 144)
#define B_STG (128 * 144)
#define NSTAGE 4
#define MT 256
#define GY (NTOK / MT)       // 16

// grid (45, 16, 8): x<44 gemm tiles; x==44 -> w2 cvt (128 blocks grid-stride)
__global__ void __launch_bounds__(512, 1)
gemm1_tc(const float* __restrict__ w2, __half* __restrict__ w2h) {
    if (blockIdx.x == FFN / 64) {
        const int NW8 = NEXP * FFN * HID / 8;
        int bi = blockIdx.z * GY + blockIdx.y;           // 0..127
        for (int i = bi * 512 + threadIdx.x; i < NW8; i += 128 * 512)
            cvt8_body(w2, w2h, i);
        return;
    }

    int e = blockIdx.z;
    int cnt = d_cntf[e], off = d_off[e];
    int m0 = blockIdx.y * MT;
    if (m0 >= cnt) return;
    int n0 = blockIdx.x * 64;

    extern __shared__ char sm_[];
    uint32_t As_u = smem_u32(sm_);
    uint32_t Bs_u = As_u + NSTAGE * A_STG;
    __shared__ int s_tok[MT];
    __shared__ __align__(8) uint64_t s_mbar[8];   // full[0..3], empty[0..3]

    int tid = threadIdx.x;
    int wid = tid >> 5, lane = tid & 31;
    int g = lane >> 2, t = lane & 3;
    int wm = (wid >> 2) * 64;       // 4 m-groups over 256
    int wn = (wid & 3) * 16;        // 4 n-groups over 64

    uint32_t mb = smem_u32(&s_mbar[0]);
    if (tid == 0) {
#pragma unroll
        for (int s = 0; s < NSTAGE; s++) {
            MBAR_INIT(mb + s * 8, 512);                  // full
            MBAR_INIT(mb + NSTAGE * 8 + s * 8, 512);     // empty
        }
    }
    if (tid < MT) {
        int m = m0 + tid; if (m >= cnt) m = cnt - 1;
        s_tok[tid] = d_slot_token[off + m];
    }
    __syncthreads();

    // A: 256 rows x 8 segs = 2048 items / 512 thr = 4 each
    const __half* asrc[4]; uint32_t adst[4];
#pragma unroll
    for (int i = 0; i < 4; i++) {
        int idx = tid + i * 512;
        int row = idx >> 3, seg = idx & 7;
        asrc[i] = d_x16 + (size_t)s_tok[row] * HID + seg * 8;
        adst[i] = As_u + (uint32_t)row * PITCH + seg * 16;
    }
    // B: 128 rows x 8 = 1024 items -> 2 each
    const __half* bsrc[2]; uint32_t bdst[2];
#pragma unroll
    for (int i = 0; i < 2; i++) {
        int idx = tid + i * 512;
        int row = idx >> 3, seg = idx & 7;
        const __half* w = (row < 64)
            ? (d_w1h + ((size_t)e * FFN + n0 + row) * HID)
            : (d_w3h + ((size_t)e * FFN + n0 + row - 64) * HID);
        bsrc[i] = w + seg * 8;
        bdst[i] = Bs_u + (uint32_t)row * PITCH + seg * 16;
    }

#define G1_LOAD(c_, st_) do { \
    int _k = (c_) * 64; \
    uint32_t _ao = (st_) * (uint32_t)A_STG; \
    uint32_t _bo = (st_) * (uint32_t)B_STG; \
    _Pragma("unroll") for (int _i = 0; _i < 4; _i++) CP_ASYNC16(adst[_i] + _ao, asrc[_i] + _k); \
    _Pragma("unroll") for (int _i = 0; _i < 2; _i++) CP_ASYNC16(bdst[_i] + _bo, bsrc[_i] + _k); \
} while (0)

    int qrow = lane & 7, quad = lane >> 3;
    uint32_t a_ld[4];
#pragma unroll
    for (int i = 0; i < 4; i++)
        a_ld[i] = As_u + (uint32_t)(wm + i * 16 + (quad & 1) * 8 + qrow) * PITCH + (quad >> 1) * 16;
    uint32_t b1_ld, b3_ld;
    {
        uint32_t r = (uint32_t)(wn + (quad >> 1) * 8 + qrow) * PITCH + (quad & 1) * 16;
        b1_ld = Bs_u + r;
        b3_ld = Bs_u + r + 64 * PITCH;
    }

    float acc1[4][2][4], acc3[4][2][4];
#pragma unroll
    for (int i = 0; i < 4; i++)
#pragma unroll
        for (int j = 0; j < 2; j++)
#pragma unroll
            for (int k = 0; k < 4; k++) { acc1[i][j][k] = 0.f; acc3[i][j][k] = 0.f; }

    const int NC = HID / 64;   // 16
    G1_LOAD(0, 0); CPA_ARRIVE(mb + 0);
    G1_LOAD(1, 1); CPA_ARRIVE(mb + 8);
    G1_LOAD(2, 2); CPA_ARRIVE(mb + 16);
    G1_LOAD(3, 3); CPA_ARRIVE(mb + 24);

#pragma unroll 1
    for (int c = 0; c < NC; c++) {
        int st = c & 3;
        int pp = (c >> 2) & 1;
        MBAR_WAIT(mb + st * 8, pp);

        uint32_t aoff = st * (uint32_t)A_STG;
        uint32_t boff = st * (uint32_t)B_STG;
#pragma unroll
        for (int ks = 0; ks < 4; ks++) {
            uint32_t koff = ks * 32u;
            uint32_t a[4][4], b1r[4], b3r[4];
#pragma unroll
            for (int i = 0; i < 4; i++) LDSM4(a[i], a_ld[i] + aoff + koff);
            LDSM4(b1r, b1_ld + boff + koff);
            LDSM4(b3r, b3_ld + boff + koff);
#pragma unroll
            for (int j = 0; j < 2; j++) {
                uint32_t bb10 = b1r[j * 2], bb11 = b1r[j * 2 + 1];
                uint32_t bb30 = b3r[j * 2], bb31 = b3r[j * 2 + 1];
#pragma unroll
                for (int i = 0; i < 4; i++) {
                    mma_f16(acc1[i][j], a[i][0], a[i][1], a[i][2], a[i][3], bb10, bb11);
                    mma_f16(acc3[i][j], a[i][0], a[i][1], a[i][2], a[i][3], bb30, bb31);
                }
            }
        }
        MBAR_ARRIVE(mb + NSTAGE * 8 + st * 8);
        if (c + 4 < NC) {
            MBAR_WAIT(mb + NSTAGE * 8 + st * 8, pp);
            G1_LOAD(c + 4, st);
            CPA_ARRIVE(mb + st * 8);
        }
    }

    // ---- epilogue: SwiGLU -> d_H16 ----
#pragma unroll
    for (int i = 0; i < 4; i++) {
#pragma unroll
        for (int hh = 0; hh < 2; hh++) {
            int m = m0 + wm + i * 16 + g + hh * 8;
            if (m < cnt) {
                __half* hrow = d_H16 + (size_t)(off + m) * FFN + n0 + wn;
#pragma unroll
                for (int j = 0; j < 2; j++) {
                    float s1a = acc1[i][j][hh * 2 + 0], s1b = acc1[i][j][hh * 2 + 1];
                    float v3a = acc3[i][j][hh * 2 + 0], v3b = acc3[i][j][hh * 2 + 1];
                    float ha = (s1a / (1.f + expf(-s1a))) * v3a;
                    float hb = (s1b / (1.f + expf(-s1b))) * v3b;
                    *(__half2*)(hrow + j * 8 + 2 * t) = __floats2half2_rn(ha, hb);
                }
            }
        }
    }
}

__global__ void __launch_bounds__(512, 1)
gemm2_tc(float* __restrict__ out) {
    int e = blockIdx.z;
    int cnt = d_cntf[e], off = d_off[e];
    int m0 = blockIdx.y * MT;
    if (m0 >= cnt) return;
    int n0 = blockIdx.x * 128;

    extern __shared__ char sm_[];
    uint32_t As_u = smem_u32(sm_);
    uint32_t Bs_u = As_u + NSTAGE * A_STG;
    __shared__ __align__(8) uint64_t s_mbar[8];

    int tid = threadIdx.x;
    int wid = tid >> 5, lane = tid & 31;
    int g = lane >> 2, t = lane & 3;
    int wm = (wid >> 2) * 64;
    int wn = (wid & 3) * 32;

    uint32_t mb = smem_u32(&s_mbar[0]);
    if (tid == 0) {
#pragma unroll
        for (int s = 0; s < NSTAGE; s++) {
            MBAR_INIT(mb + s * 8, 512);
            MBAR_INIT(mb + NSTAGE * 8 + s * 8, 512);
        }
    }
    __syncthreads();

    const __half* asrc[4]; uint32_t adst[4];
#pragma unroll
    for (int i = 0; i < 4; i++) {
        int idx = tid + i * 512;
        int row = idx >> 3, seg = idx & 7;
        int m = m0 + row; if (m >= cnt) m = cnt - 1;
        asrc[i] = d_H16 + (size_t)(off + m) * FFN + seg * 8;
        adst[i] = As_u + (uint32_t)row * PITCH + seg * 16;
    }
    const __half* bsrc[2]; uint32_t bdst[2];
#pragma unroll
    for (int i = 0; i < 2; i++) {
        int idx = tid + i * 512;
        int row = idx >> 3, seg = idx & 7;    // w2 rows n0..n0+127
        bsrc[i] = d_w2h + ((size_t)e * HID + n0 + row) * FFN + seg * 8;
        bdst[i] = Bs_u + (uint32_t)row * PITCH + seg * 16;
    }

#define G2_LOAD(c_, st_) do { \
    int _k = (c_) * 64; \
    uint32_t _ao = (st_) * (uint32_t)A_STG; \
    uint32_t _bo = (st_) * (uint32_t)B_STG; \
    _Pragma("unroll") for (int _i = 0; _i < 4; _i++) CP_ASYNC16(adst[_i] + _ao, asrc[_i] + _k); \
    _Pragma("unroll") for (int _i = 0; _i < 2; _i++) CP_ASYNC16(bdst[_i] + _bo, bsrc[_i] + _k); \
} while (0)

    int qrow = lane & 7, quad = lane >> 3;
    uint32_t a_ld[4];
#pragma unroll
    for (int i = 0; i < 4; i++)
        a_ld[i] = As_u + (uint32_t)(wm + i * 16 + (quad & 1) * 8 + qrow) * PITCH + (quad >> 1) * 16;
    uint32_t b_ld[2];
#pragma unroll
    for (int jj = 0; jj < 2; jj++)
        b_ld[jj] = Bs_u + (uint32_t)(wn + jj * 16 + (quad >> 1) * 8 + qrow) * PITCH + (quad & 1) * 16;

    float acc[4][4][4];
#pragma unroll
    for (int i = 0; i < 4; i++)
#pragma unroll
        for (int j = 0; j < 4; j++)
#pragma unroll
            for (int k = 0; k < 4; k++) acc[i][j][k] = 0.f;

    const int NC = FFN / 64;   // 44
    G2_LOAD(0, 0); CPA_ARRIVE(mb + 0);
    G2_LOAD(1, 1); CPA_ARRIVE(mb + 8);
    G2_LOAD(2, 2); CPA_ARRIVE(mb + 16);
    G2_LOAD(3, 3); CPA_ARRIVE(mb + 24);

#pragma unroll 1
    for (int c = 0; c < NC; c++) {
        int st = c & 3;
        int pp = (c >> 2) & 1;
        MBAR_WAIT(mb + st * 8, pp);

        uint32_t aoff = st * (uint32_t)A_STG;
        uint32_t boff = st * (uint32_t)B_STG;
#pragma unroll
        for (int ks = 0; ks < 4; ks++) {
            uint32_t koff = ks * 32u;
            uint32_t a[4][4], br[2][4];
#pragma unroll
            for (int i = 0; i < 4; i++) LDSM4(a[i], a_ld[i] + aoff + koff);
#pragma unroll
            for (int jj = 0; jj < 2; jj++) LDSM4(br[jj], b_ld[jj] + boff + koff);
#pragma unroll
            for (int jj = 0; jj < 2; jj++)
#pragma unroll
                for (int h = 0; h < 2; h++) {
                    int j = jj * 2 + h;
                    uint32_t bb0 = br[jj][h * 2], bb1 = br[jj][h * 2 + 1];
#pragma unroll
                    for (int i = 0; i < 4; i++)
                        mma_f16(acc[i][j], a[i][0], a[i][1], a[i][2], a[i][3], bb0, bb1);
                }
        }
        MBAR_ARRIVE(mb + NSTAGE * 8 + st * 8);
        if (c + 4 < NC) {
            MBAR_WAIT(mb + NSTAGE * 8 + st * 8, pp);
            G2_LOAD(c + 4, st);
            CPA_ARRIVE(mb + st * 8);
        }
    }

    // ---- epilogue: weighted atomic accumulate ----
#pragma unroll
    for (int i = 0; i < 4; i++) {
#pragma unroll
        for (int hh = 0; hh < 2; hh++) {
            int m = m0 + wm + i * 16 + g + hh * 8;
            if (m < cnt) {
                int tok = d_slot_token[off + m];
                float wgt = d_slot_w[off + m];
                float* orow = out + (size_t)tok * HID + n0 + wn;
#pragma unroll
                for (int j = 0; j < 4; j++) {
                    atomicAdd(&orow[j * 8 + 2 * t],     wgt * acc[i][j][hh * 2 + 0]);
                    atomicAdd(&orow[j * 8 + 2 * t + 1], wgt * acc[i][j][hh * 2 + 1]);
                }
            }
        }
    }
}

// ================= launch =================
extern "C" void kernel_launch(void* const* d_in, const int* in_sizes, int n_in,
                              void* d_out, int out_size) {
    const float* x  = (const float*)d_in[0];
    const float* gw = (const float*)d_in[1];
    const float* w1 = (const float*)d_in[2];
    const float* w2 = (const float*)d_in[3];
    const float* w3 = (const float*)d_in[4];
    float* out = (float*)d_out;

    const int smem12 = NSTAGE * (A_STG + B_STG);   // 221184
    cudaFuncSetAttribute(gemm1_tc, cudaFuncAttributeMaxDynamicSharedMemorySize, smem12);
    cudaFuncSetAttribute(gemm2_tc, cudaFuncAttributeMaxDynamicSharedMemorySize, smem12);

    __half *p_x16, *p_w1h, *p_w3h, *p_w2h;
    cudaGetSymbolAddress((void**)&p_x16, d_x16);
    cudaGetSymbolAddress((void**)&p_w1h, d_w1h);
    cudaGetSymbolAddress((void**)&p_w3h, d_w3h);
    cudaGetSymbolAddress((void**)&p_w2h, d_w2h);

    // 1. fused gate + cvt(x, w1, w3)
    {
        const int NW8 = NEXP * FFN * HID / 8;
        const int NX8 = NTOK * HID / 8;
        const int CVT_BLKS = (2 * NW8 + NX8 + 255) / 256;
        gate_cvt13_kernel<<<GATE_BLKS + CVT_BLKS, 256>>>(x, gw, w1, w3,
                                                         p_x16, p_w1h, p_w3h);
    }

    // 2. scan
    scan_kernel<<<1, 1>>>();

    // 3. fused scatter + zero(out)
    scatter_zero_kernel<<<SCAT_BLKS + NTOK * HID / 4 / 256, 256>>>(out);

    // 4. gemm1 (+ embedded w2 conversion)
    dim3 g1(FFN / 64 + 1, GY, NEXP);   // 45 x 16 x 8
    gemm1_tc<<<g1, 512, smem12>>>(w2, p_w2h);

    // 5. gemm2
    dim3 g2(HID / 128, GY, NEXP);      // 8 x 16 x 8
    gemm2_tc<<<g2, 512, smem12>>>(out);
}

// round 17
// speedup vs baseline: 1.2403x; 1.2403x over previous
#include <cuda_runtime.h>
#include <cuda_fp16.h>
#include <math.h>
#include <stdint.h>

#define NTOK 4096
#define HID  1024
#define FFN  2816
#define NEXP 8
#define NSLOT (NTOK * 2)

// ================= helpers =================
__device__ __forceinline__ uint32_t smem_u32(const void* p) {
    uint32_t a;
    asm("{ .reg .u64 t; cvta.to.shared.u64 t, %1; cvt.u32.u64 %0, t; }" : "=r"(a) : "l"(p));
    return a;
}

#define CP_ASYNC16(dst_u32, src_ptr) \
    asm volatile("cp.async.cg.shared.global [%0], [%1], 16;" :: "r"(dst_u32), "l"(src_ptr))

#define LDSM4(r, addr) \
    asm volatile("ldmatrix.sync.aligned.m8n8.x4.shared.b16 {%0,%1,%2,%3}, [%4];" \
        : "=r"((r)[0]), "=r"((r)[1]), "=r"((r)[2]), "=r"((r)[3]) : "r"(addr))

__device__ __forceinline__ void mma_f16(float c[4],
                                        uint32_t a0, uint32_t a1, uint32_t a2, uint32_t a3,
                                        uint32_t b0, uint32_t b1) {
    asm volatile("mma.sync.aligned.m16n8k16.row.col.f32.f16.f16.f32 "
        "{%0,%1,%2,%3}, {%4,%5,%6,%7}, {%8,%9}, {%0,%1,%2,%3};"
        : "+f"(c[0]), "+f"(c[1]), "+f"(c[2]), "+f"(c[3])
        : "r"(a0), "r"(a1), "r"(a2), "r"(a3), "r"(b0), "r"(b1));
}

__device__ __forceinline__ uint32_t h2_as_u32(__half2 h) {
    uint32_t u; asm("mov.b32 %0, %1;" : "=r"(u) : "r"(*(uint32_t*)&h)); return u;
}

// ---- mbarrier ops ----
#define MBAR_INIT(addr, cnt) \
    asm volatile("mbarrier.init.shared.b64 [%0], %1;" :: "r"(addr), "r"((uint32_t)(cnt)) : "memory")
#define MBAR_ARRIVE(addr) \
    asm volatile("mbarrier.arrive.shared.b64 _, [%0];" :: "r"(addr) : "memory")
#define CPA_ARRIVE(addr) \
    asm volatile("cp.async.mbarrier.arrive.noinc.shared.b64 [%0];" :: "r"(addr) : "memory")

#define MBAR_WAIT(mbar_addr, parity) do { \
    uint32_t _m = (uint32_t)(mbar_addr); uint32_t _p = (uint32_t)(parity); uint32_t _d; \
    asm volatile("{\n\t.reg .pred p;\n\t" \
        "mbarrier.try_wait.parity.acquire.cta.shared::cta.b64 p, [%1], %2;\n\t" \
        "selp.b32 %0, 1, 0, p;\n\t}" : "=r"(_d) : "r"(_m), "r"(_p) : "memory"); \
    if (!_d) { \
        asm volatile("{\n\t.reg .pred P1;\n\t" \
            "WL_%=:\n\t" \
            "mbarrier.try_wait.parity.acquire.cta.shared::cta.b64 P1, [%0], %1, 0x989680;\n\t" \
            "@P1 bra.uni WD_%=;\n\t" \
            "bra.uni WL_%=;\n\t" \
            "WD_%=:\n\t}" :: "r"(_m), "r"(_p) : "memory"); \
    } \
} while (0)

// ================= scratch =================
__device__ int    d_cnt[NEXP];
__device__ int    d_cntf[NEXP];
__device__ int    d_off[NEXP];
__device__ int    d_done;          // gate-block completion ticket
__device__ int    d_tok_expert[NSLOT];
__device__ float  d_tok_w[NSLOT];
__device__ int    d_tok_pos[NSLOT];
__device__ int    d_slot_token[NSLOT];
__device__ float  d_slot_w[NSLOT];

__device__ __half d_x16[(size_t)NTOK * HID];
__device__ __half d_w1h[(size_t)NEXP * FFN * HID];
__device__ __half d_w3h[(size_t)NEXP * FFN * HID];
__device__ __half d_w2h[(size_t)NEXP * HID * FFN];
__device__ __half d_H16[(size_t)NSLOT * FFN];

// ================= fp32 -> fp16 =================
__device__ __forceinline__ void cvt8_body(const float* __restrict__ src,
                                          __half* __restrict__ dst, int i) {
    const float4* s4 = (const float4*)src + (size_t)i * 2;
    float4 a = s4[0], b = s4[1];
    uint4 o;
    o.x = h2_as_u32(__floats2half2_rn(a.x, a.y));
    o.y = h2_as_u32(__floats2half2_rn(a.z, a.w));
    o.z = h2_as_u32(__floats2half2_rn(b.x, b.y));
    o.w = h2_as_u32(__floats2half2_rn(b.z, b.w));
    ((uint4*)dst)[i] = o;
}

// ================= fused gate + cvt(x,w1,w3) + inline scan =================
#define GATE_BLKS (NTOK / 2)

__global__ void __launch_bounds__(256)
gate_cvt13_kernel(const float* __restrict__ x, const float* __restrict__ gw,
                  const float* __restrict__ w1, const float* __restrict__ w3,
                  __half* __restrict__ x16, __half* __restrict__ w1h,
                  __half* __restrict__ w3h) {
    int bx = blockIdx.x;
    int tid = threadIdx.x;
    if (bx < GATE_BLKS) {
        int half = tid >> 7;
        int htid = tid & 127;
        int t = bx * 2 + half;
        const float* xr = x + (size_t)t * HID;
        float part[NEXP];
#pragma unroll
        for (int e = 0; e < NEXP; e++) part[e] = 0.f;
#pragma unroll
        for (int i = 0; i < HID / 128; i++) {
            float xv = xr[htid + i * 128];
#pragma unroll
            for (int e = 0; e < NEXP; e++) part[e] += xv * gw[e * HID + htid + i * 128];
        }
        __shared__ float sh[8][NEXP];
        int lane = tid & 31, w = tid >> 5;
#pragma unroll
        for (int e = 0; e < NEXP; e++) {
            float v = part[e];
            for (int s = 16; s > 0; s >>= 1) v += __shfl_down_sync(0xffffffffu, v, s);
            if (lane == 0) sh[w][e] = v;
        }
        __syncthreads();
        if (htid == 0) {
            int wb = half * 4;
            float logit[NEXP];
#pragma unroll
            for (int e = 0; e < NEXP; e++)
                logit[e] = sh[wb][e] + sh[wb + 1][e] + sh[wb + 2][e] + sh[wb + 3][e];
            int i0 = 0;
            for (int e = 1; e < NEXP; e++) if (logit[e] > logit[i0]) i0 = e;
            int i1 = -1;
            for (int e = 0; e < NEXP; e++) {
                if (e == i0) continue;
                if (i1 < 0 || logit[e] > logit[i1]) i1 = e;
            }
            float p1 = expf(logit[i1] - logit[i0]);
            float inv = 1.f / (1.f + p1);
            int q0 = atomicAdd(&d_cnt[i0], 1);
            int q1 = atomicAdd(&d_cnt[i1], 1);
            d_tok_expert[t * 2 + 0] = i0;  d_tok_expert[t * 2 + 1] = i1;
            d_tok_w[t * 2 + 0] = inv;      d_tok_w[t * 2 + 1] = p1 * inv;
            d_tok_pos[t * 2 + 0] = q0;     d_tok_pos[t * 2 + 1] = q1;
        }
        __syncthreads();
        // last gate block performs the scan inline (removes scan_kernel launch)
        if (tid == 0) {
            __threadfence();
            int v = atomicAdd(&d_done, 1);
            if (v == GATE_BLKS - 1) {
                int s = 0;
#pragma unroll
                for (int e = 0; e < NEXP; e++) {
                    int c = d_cnt[e];
                    d_off[e] = s;
                    d_cntf[e] = c;
                    s += c;
                    d_cnt[e] = 0;
                }
                d_done = 0;
                __threadfence();
            }
        }
    } else {
        const int NW8 = NEXP * FFN * HID / 8;
        const int NX8 = NTOK * HID / 8;
        int i = (bx - GATE_BLKS) * 256 + tid;
        if (i < NW8)                 cvt8_body(w1, w1h, i);
        else if (i < 2 * NW8)        cvt8_body(w3, w3h, i - NW8);
        else if (i < 2 * NW8 + NX8)  cvt8_body(x,  x16, i - 2 * NW8);
    }
}

// ================= fused scatter + zero(out) =================
#define SCAT_BLKS (NSLOT / 256)

__global__ void __launch_bounds__(256)
scatter_zero_kernel(float* __restrict__ out) {
    int bx = blockIdx.x;
    int tid = threadIdx.x;
    if (bx < SCAT_BLKS) {
        int idx = bx * 256 + tid;
        int e = d_tok_expert[idx];
        int slot = d_off[e] + d_tok_pos[idx];
        d_slot_token[slot] = idx >> 1;
        d_slot_w[slot] = d_tok_w[idx];
    } else {
        int i = (bx - SCAT_BLKS) * 256 + tid;
        if (i < NTOK * HID / 4) ((float4*)out)[i] = make_float4(0.f, 0.f, 0.f, 0.f);
    }
}

// ================= tensor GEMMs: 2 CTAs/SM + mbarrier stage pipeline =================
#define PITCH 144u
#define A_STG (128 * 144)
#define B_STG (128 * 144)
#define NSTAGE 3

// grid (45, 32, 8): x<44 gemm tiles; x==44 -> w2 cvt
__global__ void __launch_bounds__(256, 2)
gemm1_tc(const float* __restrict__ w2, __half* __restrict__ w2h) {
    if (blockIdx.x == FFN / 64) {
        const int NW8 = NEXP * FFN * HID / 8;
        int bi = blockIdx.z * 32 + blockIdx.y;           // 0..255
        for (int i = bi * 256 + threadIdx.x; i < NW8; i += 256 * 256)
            cvt8_body(w2, w2h, i);
        return;
    }

    int e = blockIdx.z;
    int cnt = d_cntf[e], off = d_off[e];
    int m0 = blockIdx.y * 128;
    if (m0 >= cnt) return;
    int n0 = blockIdx.x * 64;

    extern __shared__ char sm_[];
    uint32_t As_u = smem_u32(sm_);
    uint32_t Bs_u = As_u + NSTAGE * A_STG;
    __shared__ int s_tok[128];
    __shared__ __align__(8) uint64_t s_mbar[6];   // full[0..2], empty[0..2]

    int tid = threadIdx.x;
    int wid = tid >> 5, lane = tid & 31;
    int g = lane >> 2, t = lane & 3;
    int wm = (wid >> 2) * 64;
    int wn = (wid & 3) * 16;

    uint32_t mb = smem_u32(&s_mbar[0]);
    if (tid == 0) {
#pragma unroll
        for (int s = 0; s < 3; s++) {
            MBAR_INIT(mb + s * 8, 256);          // full: all threads' cp.async
            MBAR_INIT(mb + 24 + s * 8, 8);       // empty: warp leaders only
        }
    }
    if (tid < 128) {
        int m = m0 + tid; if (m >= cnt) m = cnt - 1;
        s_tok[tid] = d_slot_token[off + m];
    }
    __syncthreads();

    const __half* asrc[4]; uint32_t adst[4];
#pragma unroll
    for (int i = 0; i < 4; i++) {
        int idx = tid + i * 256;
        int row = idx >> 3, seg = idx & 7;
        asrc[i] = d_x16 + (size_t)s_tok[row] * HID + seg * 8;
        adst[i] = As_u + (uint32_t)row * PITCH + seg * 16;
    }
    const __half* bsrc[4]; uint32_t bdst[4];
#pragma unroll
    for (int i = 0; i < 4; i++) {
        int idx = tid + i * 256;
        int row = idx >> 3, seg = idx & 7;
        const __half* w = (row < 64)
            ? (d_w1h + ((size_t)e * FFN + n0 + row) * HID)
            : (d_w3h + ((size_t)e * FFN + n0 + row - 64) * HID);
        bsrc[i] = w + seg * 8;
        bdst[i] = Bs_u + (uint32_t)row * PITCH + seg * 16;
    }

#define G1_LOAD(c_, st_) do { \
    int _k = (c_) * 64; \
    uint32_t _ao = (st_) * (uint32_t)A_STG; \
    uint32_t _bo = (st_) * (uint32_t)B_STG; \
    _Pragma("unroll") for (int _i = 0; _i < 4; _i++) CP_ASYNC16(adst[_i] + _ao, asrc[_i] + _k); \
    _Pragma("unroll") for (int _i = 0; _i < 4; _i++) CP_ASYNC16(bdst[_i] + _bo, bsrc[_i] + _k); \
} while (0)

    int qrow = lane & 7, quad = lane >> 3;
    uint32_t a_ld[4];
#pragma unroll
    for (int i = 0; i < 4; i++)
        a_ld[i] = As_u + (uint32_t)(wm + i * 16 + (quad & 1) * 8 + qrow) * PITCH + (quad >> 1) * 16;
    uint32_t b1_ld, b3_ld;
    {
        uint32_t r = (uint32_t)(wn + (quad >> 1) * 8 + qrow) * PITCH + (quad & 1) * 16;
        b1_ld = Bs_u + r;
        b3_ld = Bs_u + r + 64 * PITCH;
    }

    float acc1[4][2][4], acc3[4][2][4];
#pragma unroll
    for (int i = 0; i < 4; i++)
#pragma unroll
        for (int j = 0; j < 2; j++)
#pragma unroll
            for (int k = 0; k < 4; k++) { acc1[i][j][k] = 0.f; acc3[i][j][k] = 0.f; }

    const int NC = HID / 64;   // 16
    G1_LOAD(0, 0); CPA_ARRIVE(mb + 0);
    G1_LOAD(1, 1); CPA_ARRIVE(mb + 8);
    G1_LOAD(2, 2); CPA_ARRIVE(mb + 16);

    int st = 0, pf = 0;
    int rs = 0, pe = 0;
#pragma unroll 1
    for (int c = 0; c < NC; c++) {
        if (c >= 1 && c + 2 < NC) {
            uint32_t ea = mb + 24 + rs * 8;
            MBAR_WAIT(ea, pe);
            G1_LOAD(c + 2, rs);
            CPA_ARRIVE(mb + rs * 8);
            rs++; if (rs == 3) { rs = 0; pe ^= 1; }
        }
        MBAR_WAIT(mb + st * 8, pf);

        uint32_t aoff = st * (uint32_t)A_STG;
        uint32_t boff = st * (uint32_t)B_STG;
#pragma unroll
        for (int ks = 0; ks < 4; ks++) {
            uint32_t koff = ks * 32u;
            uint32_t a[4][4], b1r[4], b3r[4];
#pragma unroll
            for (int i = 0; i < 4; i++) LDSM4(a[i], a_ld[i] + aoff + koff);
            LDSM4(b1r, b1_ld + boff + koff);
            LDSM4(b3r, b3_ld + boff + koff);
#pragma unroll
            for (int j = 0; j < 2; j++) {
                uint32_t bb10 = b1r[j * 2], bb11 = b1r[j * 2 + 1];
                uint32_t bb30 = b3r[j * 2], bb31 = b3r[j * 2 + 1];
#pragma unroll
                for (int i = 0; i < 4; i++) {
                    mma_f16(acc1[i][j], a[i][0], a[i][1], a[i][2], a[i][3], bb10, bb11);
                    mma_f16(acc3[i][j], a[i][0], a[i][1], a[i][2], a[i][3], bb30, bb31);
                }
            }
        }
        if (lane == 0) MBAR_ARRIVE(mb + 24 + st * 8);
        st++; if (st == 3) { st = 0; pf ^= 1; }
    }

    // ---- epilogue: SwiGLU -> d_H16 ----
#pragma unroll
    for (int i = 0; i < 4; i++) {
#pragma unroll
        for (int hh = 0; hh < 2; hh++) {
            int m = m0 + wm + i * 16 + g + hh * 8;
            if (m < cnt) {
                __half* hrow = d_H16 + (size_t)(off + m) * FFN + n0 + wn;
#pragma unroll
                for (int j = 0; j < 2; j++) {
                    float s1a = acc1[i][j][hh * 2 + 0], s1b = acc1[i][j][hh * 2 + 1];
                    float v3a = acc3[i][j][hh * 2 + 0], v3b = acc3[i][j][hh * 2 + 1];
                    float ha = (s1a / (1.f + expf(-s1a))) * v3a;
                    float hb = (s1b / (1.f + expf(-s1b))) * v3b;
                    *(__half2*)(hrow + j * 8 + 2 * t) = __floats2half2_rn(ha, hb);
                }
            }
        }
    }
}

__global__ void __launch_bounds__(256, 2)
gemm2_tc(float* __restrict__ out) {
    int e = blockIdx.z;
    int cnt = d_cntf[e], off = d_off[e];
    int m0 = blockIdx.y * 128;
    if (m0 >= cnt) return;
    int n0 = blockIdx.x * 128;

    extern __shared__ char sm_[];
    uint32_t As_u = smem_u32(sm_);
    uint32_t Bs_u = As_u + NSTAGE * A_STG;
    __shared__ __align__(8) uint64_t s_mbar[6];

    int tid = threadIdx.x;
    int wid = tid >> 5, lane = tid & 31;
    int g = lane >> 2, t = lane & 3;
    int wm = (wid >> 2) * 64;
    int wn = (wid & 3) * 32;

    uint32_t mb = smem_u32(&s_mbar[0]);
    if (tid == 0) {
#pragma unroll
        for (int s = 0; s < 3; s++) {
            MBAR_INIT(mb + s * 8, 256);
            MBAR_INIT(mb + 24 + s * 8, 8);
        }
    }
    __syncthreads();

    const __half* asrc[4]; uint32_t adst[4];
#pragma unroll
    for (int i = 0; i < 4; i++) {
        int idx = tid + i * 256;
        int row = idx >> 3, seg = idx & 7;
        int m = m0 + row; if (m >= cnt) m = cnt - 1;
        asrc[i] = d_H16 + (size_t)(off + m) * FFN + seg * 8;
        adst[i] = As_u + (uint32_t)row * PITCH + seg * 16;
    }
    const __half* bsrc[4]; uint32_t bdst[4];
#pragma unroll
    for (int i = 0; i < 4; i++) {
        int idx = tid + i * 256;
        int row = idx >> 3, seg = idx & 7;
        bsrc[i] = d_w2h + ((size_t)e * HID + n0 + row) * FFN + seg * 8;
        bdst[i] = Bs_u + (uint32_t)row * PITCH + seg * 16;
    }

#define G2_LOAD(c_, st_) do { \
    int _k = (c_) * 64; \
    uint32_t _ao = (st_) * (uint32_t)A_STG; \
    uint32_t _bo = (st_) * (uint32_t)B_STG; \
    _Pragma("unroll") for (int _i = 0; _i < 4; _i++) CP_ASYNC16(adst[_i] + _ao, asrc[_i] + _k); \
    _Pragma("unroll") for (int _i = 0; _i < 4; _i++) CP_ASYNC16(bdst[_i] + _bo, bsrc[_i] + _k); \
} while (0)

    int qrow = lane & 7, quad = lane >> 3;
    uint32_t a_ld[4];
#pragma unroll
    for (int i = 0; i < 4; i++)
        a_ld[i] = As_u + (uint32_t)(wm + i * 16 + (quad & 1) * 8 + qrow) * PITCH + (quad >> 1) * 16;
    uint32_t b_ld[2];
#pragma unroll
    for (int jj = 0; jj < 2; jj++)
        b_ld[jj] = Bs_u + (uint32_t)(wn + jj * 16 + (quad >> 1) * 8 + qrow) * PITCH + (quad & 1) * 16;

    float acc[4][4][4];
#pragma unroll
    for (int i = 0; i < 4; i++)
#pragma unroll
        for (int j = 0; j < 4; j++)
#pragma unroll
            for (int k = 0; k < 4; k++) acc[i][j][k] = 0.f;

    const int NC = FFN / 64;   // 44
    G2_LOAD(0, 0); CPA_ARRIVE(mb + 0);
    G2_LOAD(1, 1); CPA_ARRIVE(mb + 8);
    G2_LOAD(2, 2); CPA_ARRIVE(mb + 16);

    int st = 0, pf = 0;
    int rs = 0, pe = 0;
#pragma unroll 1
    for (int c = 0; c < NC; c++) {
        if (c >= 1 && c + 2 < NC) {
            uint32_t ea = mb + 24 + rs * 8;
            MBAR_WAIT(ea, pe);
            G2_LOAD(c + 2, rs);
            CPA_ARRIVE(mb + rs * 8);
            rs++; if (rs == 3) { rs = 0; pe ^= 1; }
        }
        MBAR_WAIT(mb + st * 8, pf);

        uint32_t aoff = st * (uint32_t)A_STG;
        uint32_t boff = st * (uint32_t)B_STG;
#pragma unroll
        for (int ks = 0; ks < 4; ks++) {
            uint32_t koff = ks * 32u;
            uint32_t a[4][4], br[2][4];
#pragma unroll
            for (int i = 0; i < 4; i++) LDSM4(a[i], a_ld[i] + aoff + koff);
#pragma unroll
            for (int jj = 0; jj < 2; jj++) LDSM4(br[jj], b_ld[jj] + boff + koff);
#pragma unroll
            for (int jj = 0; jj < 2; jj++)
#pragma unroll
                for (int h = 0; h < 2; h++) {
                    int j = jj * 2 + h;
                    uint32_t bb0 = br[jj][h * 2], bb1 = br[jj][h * 2 + 1];
#pragma unroll
                    for (int i = 0; i < 4; i++)
                        mma_f16(acc[i][j], a[i][0], a[i][1], a[i][2], a[i][3], bb0, bb1);
                }
        }
        if (lane == 0) MBAR_ARRIVE(mb + 24 + st * 8);
        st++; if (st == 3) { st = 0; pf ^= 1; }
    }

    // ---- epilogue: weighted atomic accumulate ----
#pragma unroll
    for (int i = 0; i < 4; i++) {
#pragma unroll
        for (int hh = 0; hh < 2; hh++) {
            int m = m0 + wm + i * 16 + g + hh * 8;
            if (m < cnt) {
                int tok = d_slot_token[off + m];
                float wgt = d_slot_w[off + m];
                float* orow = out + (size_t)tok * HID + n0 + wn;
#pragma unroll
                for (int j = 0; j < 4; j++) {
                    atomicAdd(&orow[j * 8 + 2 * t],     wgt * acc[i][j][hh * 2 + 0]);
                    atomicAdd(&orow[j * 8 + 2 * t + 1], wgt * acc[i][j][hh * 2 + 1]);
                }
            }
        }
    }
}

// ================= launch =================
extern "C" void kernel_launch(void* const* d_in, const int* in_sizes, int n_in,
                              void* d_out, int out_size) {
    const float* x  = (const float*)d_in[0];
    const float* gw = (const float*)d_in[1];
    const float* w1 = (const float*)d_in[2];
    const float* w2 = (const float*)d_in[3];
    const float* w3 = (const float*)d_in[4];
    float* out = (float*)d_out;

    const int smem12 = NSTAGE * (A_STG + B_STG);   // 110592
    cudaFuncSetAttribute(gemm1_tc, cudaFuncAttributeMaxDynamicSharedMemorySize, smem12);
    cudaFuncSetAttribute(gemm2_tc, cudaFuncAttributeMaxDynamicSharedMemorySize, smem12);

    __half *p_x16, *p_w1h, *p_w3h, *p_w2h;
    cudaGetSymbolAddress((void**)&p_x16, d_x16);
    cudaGetSymbolAddress((void**)&p_w1h, d_w1h);
    cudaGetSymbolAddress((void**)&p_w3h, d_w3h);
    cudaGetSymbolAddress((void**)&p_w2h, d_w2h);

    // 1. fused gate + cvt(x, w1, w3) + inline scan (last gate block)
    {
        const int NW8 = NEXP * FFN * HID / 8;
        const int NX8 = NTOK * HID / 8;
        const int CVT_BLKS = (2 * NW8 + NX8 + 255) / 256;
        gate_cvt13_kernel<<<GATE_BLKS + CVT_BLKS, 256>>>(x, gw, w1, w3,
                                                         p_x16, p_w1h, p_w3h);
    }

    // 2. fused scatter + zero(out)
    scatter_zero_kernel<<<SCAT_BLKS + NTOK * HID / 4 / 256, 256>>>(out);

    // 3. gemm1 (+ embedded w2 conversion)
    dim3 g1(FFN / 64 + 1, 32, NEXP);
    gemm1_tc<<<g1, 256, smem12>>>(w2, p_w2h);

    // 4. gemm2
    dim3 g2(HID / 128, 32, NEXP);
    gemm2_tc<<<g2, 256, smem12>>>(out);
}